// round 16
// baseline (speedup 1.0000x reference)
#include <cuda_runtime.h>
#include <cuda_fp16.h>
#include <cstdint>
#include <math.h>

#define NN 100000
#define EE 1600000
#define HH 128
#define GG 256
#define CC 5
#define FIN 4

// -------- scratch (static device globals; no allocation) --------
__device__ __half g_h16[(size_t)NN * HH];   // fp16 activations (h)
__device__ __half g_agg16[(size_t)NN * HH]; // fp16 aggregation output (GEMM A)
__device__ float  g_aggx[(size_t)NN * FIN];
__device__ __half g_Wt16[HH * HH];          // transposed fp16 weights (per layer)

__device__ int   g_deg[NN];
__device__ float g_dinv[NN];
__device__ int   g_indeg[NN];
__device__ int   g_rowptr[NN];
__device__ int   g_fill[NN];
__device__ int   g_col[EE];
__device__ float g_coef[EE];

__device__ int   g_bsums[128];
__device__ int   g_boff[128];

__device__ float g_pool[GG * HH];
__device__ int   g_cnt[GG];

__device__ int   g_is64;   // 1 if index tensors are int64, 0 if int32

__device__ __forceinline__ int load_idx(const void* p, size_t i) {
    if (g_is64) return (int)((const long long*)p)[i];
    return ((const int*)p)[i];
}

__device__ __forceinline__ float4 h4_to_f4(uint2 u) {
    __half2 h0 = *(__half2*)&u.x;
    __half2 h1 = *(__half2*)&u.y;
    float2 f0 = __half22float2(h0);
    float2 f1 = __half22float2(h1);
    return make_float4(f0.x, f0.y, f1.x, f1.y);
}

// -------- dtype detection (warp-parallel) --------
__global__ void k_detect(const int* __restrict__ ei32) {
    int lane = threadIdx.x;
    int orv = 0;
    for (int i = lane; i < 1024; i += 32) orv |= ei32[2 * i + 1];
#pragma unroll
    for (int off = 16; off; off >>= 1) orv |= __shfl_xor_sync(0xffffffffu, orv, off);
    if (lane == 0) g_is64 = (orv == 0) ? 1 : 0;
}

// -------- init --------
__global__ void k_init() {
    int i = blockIdx.x * blockDim.x + threadIdx.x;
    if (i < NN) { g_deg[i] = 1; g_fill[i] = 0; }
    if (i < GG * HH) g_pool[i] = 0.f;
    if (i < GG) g_cnt[i] = 0;
}

// -------- degree count over dst --------
__global__ void k_count(const void* __restrict__ ei) {
    int e = blockIdx.x * blockDim.x + threadIdx.x;
    if (e >= EE) return;
    int d = load_idx(ei, (size_t)EE + e);
    atomicAdd(&g_deg[d], 1);
}

__global__ void k_dinv() {
    int i = blockIdx.x * blockDim.x + threadIdx.x;
    if (i >= NN) return;
    int dg = g_deg[i];
    g_dinv[i] = rsqrtf((float)dg);
    g_indeg[i] = dg - 1;
}

// -------- prefix scan of indeg -> rowptr --------
#define SCAN_B 1024
__global__ void k_scan1() {
    __shared__ int sh[SCAN_B];
    int i = blockIdx.x * SCAN_B + threadIdx.x;
    int v = (i < NN) ? g_indeg[i] : 0;
    sh[threadIdx.x] = v;
    __syncthreads();
    for (int off = 1; off < SCAN_B; off <<= 1) {
        int t = (threadIdx.x >= off) ? sh[threadIdx.x - off] : 0;
        __syncthreads();
        sh[threadIdx.x] += t;
        __syncthreads();
    }
    if (i < NN) g_rowptr[i] = sh[threadIdx.x] - v;  // exclusive
    if (threadIdx.x == SCAN_B - 1) g_bsums[blockIdx.x] = sh[threadIdx.x];
}

__global__ void k_scan2(int nb) {
    if (threadIdx.x == 0) {
        int run = 0;
        for (int b = 0; b < nb; b++) { int v = g_bsums[b]; g_boff[b] = run; run += v; }
    }
}

__global__ void k_scan3() {
    int i = blockIdx.x * SCAN_B + threadIdx.x;
    if (i < NN) g_rowptr[i] += g_boff[blockIdx.x];
}

// -------- scatter edges into CSR (by dst) --------
__global__ void k_scatter(const void* __restrict__ ei) {
    int e = blockIdx.x * blockDim.x + threadIdx.x;
    if (e >= EE) return;
    int s = load_idx(ei, (size_t)e);
    int d = load_idx(ei, (size_t)EE + e);
    int pos = g_rowptr[d] + atomicAdd(&g_fill[d], 1);
    g_col[pos] = s;
    g_coef[pos] = g_dinv[s] * g_dinv[d];
}

// -------- layer-1 aggregation on raw x [N,4] --------
__global__ void k_aggx(const float* __restrict__ x) {
    int i = blockIdx.x * blockDim.x + threadIdx.x;
    if (i >= NN) return;
    float di = g_dinv[i];
    float4 xa = ((const float4*)x)[i];
    float w = di * di;
    float4 acc;
    acc.x = xa.x * w; acc.y = xa.y * w; acc.z = xa.z * w; acc.w = xa.w * w;
    int s0 = g_rowptr[i], cnt = g_indeg[i];
    for (int e = 0; e < cnt; e++) {
        int s = g_col[s0 + e];
        float c = g_coef[s0 + e];
        float4 xs = ((const float4*)x)[s];
        acc.x += c * xs.x; acc.y += c * xs.y; acc.z += c * xs.z; acc.w += c * xs.w;
    }
    ((float4*)g_aggx)[i] = acc;
}

// -------- layer-1 dense: h16 = relu(aggx @ W1 + b1) --------
__global__ void k_dense1(const float* __restrict__ W1, const float* __restrict__ b1) {
    __shared__ float w[FIN * HH];
    __shared__ float bb[HH];
    int tid = threadIdx.x;  // 128
    for (int t = tid; t < FIN * HH; t += 128) w[t] = W1[t];
    bb[tid] = b1[tid];
    __syncthreads();
    int base = blockIdx.x * 8;
    for (int nn = 0; nn < 8; nn++) {
        int i = base + nn;
        if (i >= NN) break;
        float4 xa = ((const float4*)g_aggx)[i];
        float v = xa.x * w[tid] + xa.y * w[HH + tid] + xa.z * w[2 * HH + tid]
                + xa.w * w[3 * HH + tid] + bb[tid];
        g_h16[(size_t)i * HH + tid] = __float2half_rn(fmaxf(v, 0.f));
    }
}

// -------- aggregation on fp16 activations (warp per node) --------
// reads g_h16, writes g_agg16 (fp32 accumulate)
__global__ void k_aggh() {
    int gt = blockIdx.x * blockDim.x + threadIdx.x;
    int i = gt >> 5;
    int lane = gt & 31;
    if (i >= NN) return;
    float di = g_dinv[i];
    float w = di * di;
    float4 v0 = h4_to_f4(((const uint2*)(g_h16 + (size_t)i * HH))[lane]);
    float4 acc;
    acc.x = v0.x * w; acc.y = v0.y * w; acc.z = v0.z * w; acc.w = v0.w * w;
    int s0 = g_rowptr[i], cnt = g_indeg[i];
    int e = 0;
    for (; e + 4 <= cnt; e += 4) {
        int sA = g_col[s0 + e];     float cA = g_coef[s0 + e];
        int sB = g_col[s0 + e + 1]; float cB = g_coef[s0 + e + 1];
        int sC = g_col[s0 + e + 2]; float cC = g_coef[s0 + e + 2];
        int sD = g_col[s0 + e + 3]; float cD = g_coef[s0 + e + 3];
        float4 vA = h4_to_f4(((const uint2*)(g_h16 + (size_t)sA * HH))[lane]);
        float4 vB = h4_to_f4(((const uint2*)(g_h16 + (size_t)sB * HH))[lane]);
        float4 vC = h4_to_f4(((const uint2*)(g_h16 + (size_t)sC * HH))[lane]);
        float4 vD = h4_to_f4(((const uint2*)(g_h16 + (size_t)sD * HH))[lane]);
        acc.x += cA * vA.x; acc.y += cA * vA.y; acc.z += cA * vA.z; acc.w += cA * vA.w;
        acc.x += cB * vB.x; acc.y += cB * vB.y; acc.z += cB * vB.z; acc.w += cB * vB.w;
        acc.x += cC * vC.x; acc.y += cC * vC.y; acc.z += cC * vC.z; acc.w += cC * vC.w;
        acc.x += cD * vD.x; acc.y += cD * vD.y; acc.z += cD * vD.z; acc.w += cD * vD.w;
    }
    for (; e < cnt; e++) {
        int s = g_col[s0 + e]; float c = g_coef[s0 + e];
        float4 v = h4_to_f4(((const uint2*)(g_h16 + (size_t)s * HH))[lane]);
        acc.x += c * v.x; acc.y += c * v.y; acc.z += c * v.z; acc.w += c * v.w;
    }
    __half2 p0 = __floats2half2_rn(acc.x, acc.y);
    __half2 p1 = __floats2half2_rn(acc.z, acc.w);
    uint2 pk; pk.x = *(unsigned*)&p0; pk.y = *(unsigned*)&p1;
    ((uint2*)(g_agg16 + (size_t)i * HH))[lane] = pk;
}

// -------- weight convert + transpose: Wt16[n][k] = (half)W[k][n] --------
__global__ void k_convW(const float* __restrict__ W) {
    int t = blockIdx.x * blockDim.x + threadIdx.x;   // 16384
    int n = t >> 7, k = t & 127;
    g_Wt16[n * HH + k] = __float2half_rn(W[k * HH + n]);
}

// -------- tensor-core GEMM: h16 = relu(agg16[N,128] @ W[128,128] + b) --------
// mma.sync.m16n8k16.row.col.f32.f16.f16.f32
// Block: 256 thr (8 warps), 128 rows; K chunked by 64.
#define KCH 64
#define AROW_W 36      // smem row stride in 32-bit words (72 halves); 36%32=4 -> conflict-free
__global__ void k_gemm_mma(const float* __restrict__ bias) {
    __shared__ __half As[128 * 72];   // [row][72], 64 data halves + 8 pad
    __shared__ __half Ws[128 * 72];   // [n][72]
    int tid = threadIdx.x;
    int w = tid >> 5;                 // warp id: rows w*16..w*16+15
    int lane = tid & 31;
    int g = lane >> 2;                // groupID
    int tig = lane & 3;               // thread in group
    int rowbase = blockIdx.x * 128;

    float c[16][4];
#pragma unroll
    for (int j = 0; j < 16; j++)
#pragma unroll
        for (int q = 0; q < 4; q++) c[j][q] = 0.f;

    const unsigned int* AsW = (const unsigned int*)As;
    const unsigned int* WsW = (const unsigned int*)Ws;

    for (int kc = 0; kc < 2; kc++) {
        // fill A chunk: 128 rows x 64 halves = 1024 uint4; 4 per thread
#pragma unroll
        for (int it = 0; it < 4; it++) {
            int idx = tid + it * 256;          // [0,1024)
            int r = idx >> 3, q = idx & 7;
            int row = rowbase + r;
            uint4 v = make_uint4(0u, 0u, 0u, 0u);
            if (row < NN)
                v = ((const uint4*)(g_agg16 + (size_t)row * HH + kc * KCH))[q];
            ((uint4*)As)[r * 9 + q] = v;
        }
        // fill W chunk: 128 n x 64 halves
#pragma unroll
        for (int it = 0; it < 4; it++) {
            int idx = tid + it * 256;
            int n = idx >> 3, q = idx & 7;
            uint4 v = ((const uint4*)(g_Wt16 + (size_t)n * HH + kc * KCH))[q];
            ((uint4*)Ws)[n * 9 + q] = v;
        }
        __syncthreads();

#pragma unroll
        for (int ks = 0; ks < 4; ks++) {
            int kw = ks * 8;  // word offset of this k-step within chunk (16 halves = 8 words)
            // A fragment
            int arow0 = (w * 16 + g) * AROW_W + kw + tig;
            int arow1 = (w * 16 + g + 8) * AROW_W + kw + tig;
            unsigned int a0 = AsW[arow0];
            unsigned int a1 = AsW[arow1];
            unsigned int a2 = AsW[arow0 + 4];
            unsigned int a3 = AsW[arow1 + 4];
#pragma unroll
            for (int j = 0; j < 16; j++) {
                int nrow = (j * 8 + g) * AROW_W + kw + tig;
                unsigned int b0 = WsW[nrow];
                unsigned int b1 = WsW[nrow + 4];
                asm volatile(
                    "mma.sync.aligned.m16n8k16.row.col.f32.f16.f16.f32 "
                    "{%0,%1,%2,%3}, {%4,%5,%6,%7}, {%8,%9}, {%0,%1,%2,%3};"
                    : "+f"(c[j][0]), "+f"(c[j][1]), "+f"(c[j][2]), "+f"(c[j][3])
                    : "r"(a0), "r"(a1), "r"(a2), "r"(a3), "r"(b0), "r"(b1));
            }
        }
        __syncthreads();
    }

    // epilogue: bias + relu -> g_h16
    int row0 = rowbase + w * 16 + g;
    int row1 = row0 + 8;
#pragma unroll
    for (int j = 0; j < 16; j++) {
        int col = j * 8 + 2 * tig;
        float bx = __ldg(bias + col);
        float by = __ldg(bias + col + 1);
        if (row0 < NN) {
            __half2 o = __floats2half2_rn(fmaxf(c[j][0] + bx, 0.f),
                                          fmaxf(c[j][1] + by, 0.f));
            *(__half2*)(g_h16 + (size_t)row0 * HH + col) = o;
        }
        if (row1 < NN) {
            __half2 o = __floats2half2_rn(fmaxf(c[j][2] + bx, 0.f),
                                          fmaxf(c[j][3] + by, 0.f));
            *(__half2*)(g_h16 + (size_t)row1 * HH + col) = o;
        }
    }
}

// -------- mean pool (warp per node, float atomics), reads h16 --------
__global__ void k_pool(const void* __restrict__ batch) {
    int gt = blockIdx.x * blockDim.x + threadIdx.x;
    int i = gt >> 5;
    int lane = gt & 31;
    if (i >= NN) return;
    int g = load_idx(batch, (size_t)i);
    float4 v = h4_to_f4(((const uint2*)(g_h16 + (size_t)i * HH))[lane]);
    float* base = g_pool + (size_t)g * HH + lane * 4;
    atomicAdd(base + 0, v.x);
    atomicAdd(base + 1, v.y);
    atomicAdd(base + 2, v.z);
    atomicAdd(base + 3, v.w);
    if (lane == 0) atomicAdd(&g_cnt[g], 1);
}

// -------- classifier + sigmoid --------
__global__ void k_classify(const float* __restrict__ Wl, const float* __restrict__ bl,
                           float* __restrict__ out) {
    int t = blockIdx.x * blockDim.x + threadIdx.x;
    if (t >= GG * CC) return;
    int g = t / CC, c = t % CC;
    float inv = 1.f / fmaxf((float)g_cnt[g], 1.f);
    float s = bl[c];
    const float* p = g_pool + (size_t)g * HH;
#pragma unroll 8
    for (int j = 0; j < HH; j++) s += p[j] * inv * Wl[j * CC + c];
    out[t] = 1.f / (1.f + expf(-s));
}

extern "C" void kernel_launch(void* const* d_in, const int* in_sizes, int n_in,
                              void* d_out, int out_size) {
    const float* x   = (const float*)d_in[0];
    const void*  ei  = d_in[1];
    const void*  bat = d_in[2];
    const float* W1 = (const float*)d_in[3];
    const float* b1 = (const float*)d_in[4];
    const float* W2 = (const float*)d_in[5];
    const float* b2 = (const float*)d_in[6];
    const float* W3 = (const float*)d_in[7];
    const float* b3 = (const float*)d_in[8];
    const float* W4 = (const float*)d_in[9];
    const float* b4 = (const float*)d_in[10];
    const float* Wl = (const float*)d_in[11];
    const float* bl = (const float*)d_in[12];
    float* out = (float*)d_out;

    const int nb_scan = (NN + SCAN_B - 1) / SCAN_B;   // 98

    k_detect<<<1, 32>>>((const int*)ei);
    k_init<<<(NN + 255) / 256, 256>>>();
    k_count<<<(EE + 255) / 256, 256>>>(ei);
    k_dinv<<<(NN + 255) / 256, 256>>>();
    k_scan1<<<nb_scan, SCAN_B>>>();
    k_scan2<<<1, 32>>>(nb_scan);
    k_scan3<<<nb_scan, SCAN_B>>>();
    k_scatter<<<(EE + 255) / 256, 256>>>(ei);

    k_aggx<<<(NN + 255) / 256, 256>>>(x);
    k_dense1<<<(NN + 7) / 8, 128>>>(W1, b1);

    const float* Ws_[3] = {W2, W3, W4};
    const float* bs_[3] = {b2, b3, b4};
    const int gemm_blocks = (NN + 127) / 128;   // 782
    for (int l = 0; l < 3; l++) {
        k_aggh<<<(NN * 32 + 255) / 256, 256>>>();
        k_convW<<<(HH * HH + 255) / 256, 256>>>(Ws_[l]);
        k_gemm_mma<<<gemm_blocks, 256>>>(bs_[l]);
    }

    k_pool<<<(NN * 32 + 255) / 256, 256>>>(bat);
    k_classify<<<(GG * CC + 255) / 256, 256>>>(Wl, bl, out);
}